// round 1
// baseline (speedup 1.0000x reference)
#include <cuda_runtime.h>

#define DIMX 200
#define DIMY 200
#define DIMZ 16
#define TOTAL (DIMX * DIMY * DIMZ)          // 640000
#define NDIMS 16
#define KWIN 6
#define VOXEL 0.4f
#define VMINX -40.0f
#define VMINY -40.0f
#define VMINZ -1.0f

// ---------------------------------------------------------------------------
// Kernel 1: init accumulators. density = 0, feats = 0 except channel 15 = 1e-5
// ---------------------------------------------------------------------------
__global__ void gv_init(float* __restrict__ dens, float4* __restrict__ feat4) {
    int i = blockIdx.x * blockDim.x + threadIdx.x;
    if (i >= TOTAL) return;
    dens[i] = 0.0f;
    float4 z = make_float4(0.f, 0.f, 0.f, 0.f);
    float4* p = feat4 + (size_t)i * 4;
    p[0] = z;
    p[1] = z;
    p[2] = z;
    p[3] = make_float4(0.f, 0.f, 0.f, 1e-5f);
}

// vectorized global reduction (sm_90+): 4 floats, one L2 atomic op
__device__ __forceinline__ void red_add_v4(float* p, float a, float b, float c, float d) {
    asm volatile("red.global.add.v4.f32 [%0], {%1, %2, %3, %4};"
                 :: "l"(p), "f"(a), "f"(b), "f"(c), "f"(d) : "memory");
}

// ---------------------------------------------------------------------------
// Kernel 2: splat. One block per gaussian, 216 voxel lanes (6x6x6 window).
// ---------------------------------------------------------------------------
__global__ __launch_bounds__(224, 8) void gv_splat(
    const float* __restrict__ means,
    const float* __restrict__ covs,
    const float* __restrict__ opac,
    const float* __restrict__ feats,
    float* __restrict__ gdens,
    float* __restrict__ gfeat)
{
    __shared__ float s_icov[6];      // i00 i01 i02 i11 i12 i22
    __shared__ float s_mean[3];
    __shared__ float s_feat[NDIMS];
    __shared__ int   s_start[3];
    __shared__ int   s_end[3];
    __shared__ float s_op;

    const int g = blockIdx.x;
    const int t = threadIdx.x;

    if (t < NDIMS) s_feat[t] = feats[g * NDIMS + t];
    if (t == 0) {
        const float* c = covs + g * 9;
        float a00 = c[0], a01 = c[1], a02 = c[2];
        float a11 = c[4], a12 = c[5], a22 = c[8];
        // symmetric 3x3 inverse via cofactors
        float c00 = a11 * a22 - a12 * a12;
        float c01 = a02 * a12 - a01 * a22;
        float c02 = a01 * a12 - a02 * a11;
        float det = a00 * c00 + a01 * c01 + a02 * c02;
        float inv = 1.0f / det;
        s_icov[0] = c00 * inv;
        s_icov[1] = c01 * inv;
        s_icov[2] = c02 * inv;
        s_icov[3] = (a00 * a22 - a02 * a02) * inv;
        s_icov[4] = (a01 * a02 - a00 * a12) * inv;
        s_icov[5] = (a00 * a11 - a01 * a01) * inv;

        float mx = means[g * 3 + 0];
        float my = means[g * 3 + 1];
        float mz = means[g * 3 + 2];
        s_mean[0] = mx; s_mean[1] = my; s_mean[2] = mz;
        s_op = opac[g];

        float rx = 3.0f * sqrtf(a00);
        float ry = 3.0f * sqrtf(a11);
        float rz = 3.0f * sqrtf(a22);

        // all coordinates strictly positive after shift -> trunc == floor
        s_start[0] = max(0, (int)((mx - rx - VMINX) / VOXEL));
        s_start[1] = max(0, (int)((my - ry - VMINY) / VOXEL));
        s_start[2] = max(0, (int)((mz - rz - VMINZ) / VOXEL));
        s_end[0]   = min(DIMX, (int)((mx + rx - VMINX) / VOXEL) + 1);
        s_end[1]   = min(DIMY, (int)((my + ry - VMINY) / VOXEL) + 1);
        s_end[2]   = min(DIMZ, (int)((mz + rz - VMINZ) / VOXEL) + 1);
    }
    __syncthreads();

    if (t >= KWIN * KWIN * KWIN) return;

    const int lx = t / (KWIN * KWIN);
    const int ly = (t / KWIN) % KWIN;
    const int lz = t % KWIN;

    const int ix = s_start[0] + lx;
    const int iy = s_start[1] + ly;
    const int iz = s_start[2] + lz;
    if (ix >= s_end[0] || iy >= s_end[1] || iz >= s_end[2]) return;

    const float dx = (float)ix * VOXEL + VMINX - s_mean[0];
    const float dy = (float)iy * VOXEL + VMINY - s_mean[1];
    const float dz = (float)iz * VOXEL + VMINZ - s_mean[2];

    const float i00 = s_icov[0], i01 = s_icov[1], i02 = s_icov[2];
    const float i11 = s_icov[3], i12 = s_icov[4], i22 = s_icov[5];

    float mahal = i00 * dx * dx + i11 * dy * dy + i22 * dz * dz
                + 2.0f * (i01 * dx * dy + i02 * dx * dz + i12 * dy * dz);

    const float density = s_op * __expf(-0.5f * mahal);

    const int idx = (ix * DIMY + iy) * DIMZ + iz;
    atomicAdd(gdens + idx, density);

    float* fp = gfeat + (size_t)idx * NDIMS;
    red_add_v4(fp +  0, density * s_feat[0],  density * s_feat[1],
                        density * s_feat[2],  density * s_feat[3]);
    red_add_v4(fp +  4, density * s_feat[4],  density * s_feat[5],
                        density * s_feat[6],  density * s_feat[7]);
    red_add_v4(fp +  8, density * s_feat[8],  density * s_feat[9],
                        density * s_feat[10], density * s_feat[11]);
    red_add_v4(fp + 12, density * s_feat[12], density * s_feat[13],
                        density * s_feat[14], density * s_feat[15]);
}

// ---------------------------------------------------------------------------
// Kernel 3: normalize feats by clipped density, in place.
// ---------------------------------------------------------------------------
__global__ void gv_normalize(const float* __restrict__ dens, float4* __restrict__ feat4) {
    int i = blockIdx.x * blockDim.x + threadIdx.x;
    if (i >= TOTAL) return;
    const float s = 1.0f / fmaxf(dens[i], 1e-6f);
    float4* p = feat4 + (size_t)i * 4;
#pragma unroll
    for (int j = 0; j < 4; j++) {
        float4 v = p[j];
        v.x *= s; v.y *= s; v.z *= s; v.w *= s;
        p[j] = v;
    }
}

extern "C" void kernel_launch(void* const* d_in, const int* in_sizes, int n_in,
                              void* d_out, int out_size) {
    const float* means = (const float*)d_in[0];   // [N,3]
    const float* covs  = (const float*)d_in[1];   // [N,3,3]
    const float* opac  = (const float*)d_in[2];   // [N]
    const float* feats = (const float*)d_in[3];   // [N,16]
    const int n_gauss = in_sizes[2];              // opacities element count == N

    float* gdens = (float*)d_out;                 // [200*200*16]
    float* gfeat = gdens + TOTAL;                 // [200*200*16, 16]

    const int ithreads = 256;
    const int iblocks = (TOTAL + ithreads - 1) / ithreads;
    gv_init<<<iblocks, ithreads>>>(gdens, (float4*)gfeat);

    gv_splat<<<n_gauss, 224>>>(means, covs, opac, feats, gdens, gfeat);

    gv_normalize<<<iblocks, ithreads>>>(gdens, (float4*)gfeat);
}

// round 2
// speedup vs baseline: 1.5293x; 1.5293x over previous
#include <cuda_runtime.h>

#define DIMX 200
#define DIMY 200
#define DIMZ 16
#define NDIMS 16
#define KWIN 6
#define VOXEL 0.4f
#define VMINX -40.0f
#define VMINY -40.0f
#define VMINZ -1.0f

// Tiles: 4 x 4 x 8 voxels = 128 voxels = 128 threads/block
#define TX 4
#define TY 4
#define TZ 8
#define NTX (DIMX / TX)          // 50
#define NTY (DIMY / TY)          // 50
#define NTZ (DIMZ / TZ)          // 2
#define NTILES (NTX * NTY * NTZ) // 5000
#define CAP 256                  // ids per bin (expected ~28, Poisson-safe)
#define CHUNK 64                 // gaussians staged in smem per iteration
#define NMAX 65536

// Scratch (static device globals; no allocations allowed)
__device__ int   g_cnt[NTILES];
__device__ int   g_ids[NTILES * CAP];
__device__ float g_prec[NMAX * 12];  // mx,my,mz,i00 | i01,i02,i11,i12 | i22,op,startP,endP

// ---------------------------------------------------------------------------
// Kernel 1: zero bin counters
// ---------------------------------------------------------------------------
__global__ void k_zero() {
    int i = blockIdx.x * blockDim.x + threadIdx.x;
    if (i < NTILES) g_cnt[i] = 0;
}

// ---------------------------------------------------------------------------
// Kernel 2: per-gaussian precompute (icov, bbox) + scatter id into tile bins
// ---------------------------------------------------------------------------
__global__ void k_bin(const float* __restrict__ means,
                      const float* __restrict__ covs,
                      const float* __restrict__ opac,
                      int n) {
    int g = blockIdx.x * blockDim.x + threadIdx.x;
    if (g >= n) return;

    const float* c = covs + g * 9;
    float a00 = c[0], a01 = c[1], a02 = c[2];
    float a11 = c[4], a12 = c[5], a22 = c[8];
    float c00 = a11 * a22 - a12 * a12;
    float c01 = a02 * a12 - a01 * a22;
    float c02 = a01 * a12 - a02 * a11;
    float det = a00 * c00 + a01 * c01 + a02 * c02;
    float inv = 1.0f / det;
    float i00 = c00 * inv;
    float i01 = c01 * inv;
    float i02 = c02 * inv;
    float i11 = (a00 * a22 - a02 * a02) * inv;
    float i12 = (a01 * a02 - a00 * a12) * inv;
    float i22 = (a00 * a11 - a01 * a01) * inv;

    float mx = means[g * 3 + 0];
    float my = means[g * 3 + 1];
    float mz = means[g * 3 + 2];
    float rx = 3.0f * sqrtf(a00);
    float ry = 3.0f * sqrtf(a11);
    float rz = 3.0f * sqrtf(a22);

    // trunc-toward-zero matches reference (coords positive after shift)
    int sx = max(0, (int)((mx - rx - VMINX) / VOXEL));
    int sy = max(0, (int)((my - ry - VMINY) / VOXEL));
    int sz = max(0, (int)((mz - rz - VMINZ) / VOXEL));
    int ex = min(DIMX, (int)((mx + rx - VMINX) / VOXEL) + 1);
    int ey = min(DIMY, (int)((my + ry - VMINY) / VOXEL) + 1);
    int ez = min(DIMZ, (int)((mz + rz - VMINZ) / VOXEL) + 1);
    // reference only visits offs in [0, K)
    ex = min(ex, sx + KWIN);
    ey = min(ey, sy + KWIN);
    ez = min(ez, sz + KWIN);

    int sP = sx | (sy << 8) | (sz << 16);
    int eP = ex | (ey << 8) | (ez << 16);

    float4* p = (float4*)(g_prec + (size_t)g * 12);
    p[0] = make_float4(mx, my, mz, i00);
    p[1] = make_float4(i01, i02, i11, i12);
    p[2] = make_float4(i22, opac[g], __int_as_float(sP), __int_as_float(eP));

    if (sx >= ex || sy >= ey || sz >= ez) return;

    int tx0 = sx / TX, tx1 = (ex - 1) / TX;
    int ty0 = sy / TY, ty1 = (ey - 1) / TY;
    int tz0 = sz / TZ, tz1 = (ez - 1) / TZ;
    for (int tx = tx0; tx <= tx1; tx++)
        for (int ty = ty0; ty <= ty1; ty++)
            for (int tz = tz0; tz <= tz1; tz++) {
                int t = (tx * NTY + ty) * NTZ + tz;
                int slot = atomicAdd(&g_cnt[t], 1);
                if (slot < CAP) g_ids[t * CAP + slot] = g;
            }
}

// ---------------------------------------------------------------------------
// Kernel 3: gather. One block per tile, one thread per voxel.
// Accumulates density + 16 feature channels in registers, normalizes inline,
// writes final output. No atomics, no init, no separate normalize pass.
// ---------------------------------------------------------------------------
__global__ __launch_bounds__(128) void k_gather(const float4* __restrict__ feat4,
                                                float* __restrict__ gdens,
                                                float* __restrict__ gfeat) {
    __shared__ float4 s_prec[CHUNK * 3];
    __shared__ float4 s_feat[CHUNK * 4];

    const int b = blockIdx.x;
    const int tz = b % NTZ;
    const int ty = (b / NTZ) % NTY;
    const int tx = b / (NTZ * NTY);
    const int t = threadIdx.x;

    const int lz = t & 7;
    const int ly = (t >> 3) & 3;
    const int lx = t >> 5;
    const int ix = tx * TX + lx;
    const int iy = ty * TY + ly;
    const int iz = tz * TZ + lz;

    const float px = (float)ix * VOXEL + VMINX;
    const float py = (float)iy * VOXEL + VMINY;
    const float pz = (float)iz * VOXEL + VMINZ;

    const int n = min(g_cnt[b], CAP);
    const int* __restrict__ bin = g_ids + b * CAP;

    float accd = 0.0f;
    float f0x = 0, f0y = 0, f0z = 0, f0w = 0;
    float f1x = 0, f1y = 0, f1z = 0, f1w = 0;
    float f2x = 0, f2y = 0, f2z = 0, f2w = 0;
    float f3x = 0, f3y = 0, f3z = 0, f3w = 0;

    const float4* prec4 = (const float4*)g_prec;

    for (int base = 0; base < n; base += CHUNK) {
        const int m = min(CHUNK, n - base);

        // stage this chunk's precomputed records and features into smem
        for (int i = t; i < m * 3; i += 128) {
            int j = i / 3;
            s_prec[i] = prec4[(size_t)bin[base + j] * 3 + (i - j * 3)];
        }
        for (int i = t; i < m * 4; i += 128) {
            int j = i >> 2;
            s_feat[i] = feat4[(size_t)bin[base + j] * 4 + (i & 3)];
        }
        __syncthreads();

        for (int j = 0; j < m; j++) {
            float4 p2 = s_prec[j * 3 + 2];
            int sP = __float_as_int(p2.z);
            int eP = __float_as_int(p2.w);
            bool pass = (ix >= (sP & 255)) & (ix < (eP & 255))
                      & (iy >= ((sP >> 8) & 255)) & (iy < ((eP >> 8) & 255))
                      & (iz >= ((sP >> 16) & 255)) & (iz < ((eP >> 16) & 255));
            if (pass) {
                float4 p0 = s_prec[j * 3 + 0];
                float4 p1 = s_prec[j * 3 + 1];
                float dx = px - p0.x;
                float dy = py - p0.y;
                float dz = pz - p0.z;
                float mahal = p0.w * dx * dx + p1.z * dy * dy + p2.x * dz * dz
                            + 2.0f * (p1.x * dx * dy + p1.y * dx * dz + p1.w * dy * dz);
                float dens = p2.y * __expf(-0.5f * mahal);
                accd += dens;
                float4 q0 = s_feat[j * 4 + 0];
                float4 q1 = s_feat[j * 4 + 1];
                float4 q2 = s_feat[j * 4 + 2];
                float4 q3 = s_feat[j * 4 + 3];
                f0x += dens * q0.x; f0y += dens * q0.y; f0z += dens * q0.z; f0w += dens * q0.w;
                f1x += dens * q1.x; f1y += dens * q1.y; f1z += dens * q1.z; f1w += dens * q1.w;
                f2x += dens * q2.x; f2y += dens * q2.y; f2z += dens * q2.z; f2w += dens * q2.w;
                f3x += dens * q3.x; f3y += dens * q3.y; f3z += dens * q3.z; f3w += dens * q3.w;
            }
        }
        __syncthreads();
    }

    const int idx = (ix * DIMY + iy) * DIMZ + iz;
    gdens[idx] = accd;

    const float s = 1.0f / fmaxf(accd, 1e-6f);
    f3w += 1e-5f;  // reference seeds channel 15 with 1e-5 before normalize
    float4* fp = (float4*)(gfeat + (size_t)idx * NDIMS);
    fp[0] = make_float4(f0x * s, f0y * s, f0z * s, f0w * s);
    fp[1] = make_float4(f1x * s, f1y * s, f1z * s, f1w * s);
    fp[2] = make_float4(f2x * s, f2y * s, f2z * s, f2w * s);
    fp[3] = make_float4(f3x * s, f3y * s, f3z * s, f3w * s);
}

extern "C" void kernel_launch(void* const* d_in, const int* in_sizes, int n_in,
                              void* d_out, int out_size) {
    const float* means = (const float*)d_in[0];   // [N,3]
    const float* covs  = (const float*)d_in[1];   // [N,3,3]
    const float* opac  = (const float*)d_in[2];   // [N]
    const float* feats = (const float*)d_in[3];   // [N,16]
    const int n_gauss = in_sizes[2];

    float* gdens = (float*)d_out;                                  // [200*200*16]
    float* gfeat = gdens + (size_t)DIMX * DIMY * DIMZ;             // [...,16]

    k_zero<<<(NTILES + 255) / 256, 256>>>();
    k_bin<<<(n_gauss + 127) / 128, 128>>>(means, covs, opac, n_gauss);
    k_gather<<<NTILES, 128>>>((const float4*)feats, gdens, gfeat);
}